// round 7
// baseline (speedup 1.0000x reference)
#include <cuda_runtime.h>
#include <cstdint>

#define BB 8
#define DD 8
#define KK 5
#define PP (512*1024)

// ---- scratch (device globals; zero-initialized at module load; finalize
// resets them at the end of every run so graph replays start clean) ----
__device__ float g_sums[BB][KK][DD];   // per-batch per-instance channel sums
__device__ int   g_cnt[BB][KK + 1];    // per-batch per-slot pixel counts
__device__ float g_var[BB][KK + 1];    // per-batch per-slot variance sums

// ---------------------------------------------------------------------------
// Pass 1: channel-split. Warp w of each block owns channel plane w; all warps
// sweep the same pixel window (mask loads dedupe in L1). Accumulation is a
// single-float smem RMW per pixel-channel into per-thread slots (stride 7
// floats -> conflict-free banks).
#define T1 256
#define GX1 512
#define ITER1 8
// coverage: GX1 * 32 lanes * 4 px * ITER1 = 524288 = PP exactly

__global__ void __launch_bounds__(T1) pass1_kernel(const float* __restrict__ emb,
                                                   const int* __restrict__ mask) {
    __shared__ float sacc[T1 * 7];
    __shared__ float red[DD][KK];
    const int t = threadIdx.x;
    const int b = blockIdx.y;
    const int w = t >> 5, lane = t & 31;   // w = channel index

    float* my = sacc + t * 7;
#pragma unroll
    for (int j = 0; j < 7; j++) my[j] = 0.f;
    // no barrier needed before use: each thread touches only its own slots

    unsigned long long cnt64 = 0ull;
    const float* ep = emb + (size_t)b * DD * PP + (size_t)w * PP;
    const int*   mb = mask + (size_t)b * PP;
    int p = (blockIdx.x * 32 + lane) * 4;
    const int stride = GX1 * 32 * 4;

#pragma unroll
    for (int it = 0; it < ITER1; it++, p += stride) {
        const int4 lab4 = *reinterpret_cast<const int4*>(mb + p);
        const float4 v  = *reinterpret_cast<const float4*>(ep + p);
        const int labs[4] = {lab4.x, lab4.y, lab4.z, lab4.w};
        const float es[4] = {v.x, v.y, v.z, v.w};
#pragma unroll
        for (int i = 0; i < 4; i++) {
            my[labs[i]] += es[i];
            if (w == 0) cnt64 += 1ull << (labs[i] * 8);
        }
    }

    // per-warp reduction: each lane's 5 instance sums for channel w
    {
        float a[KK];
#pragma unroll
        for (int k = 0; k < KK; k++) a[k] = my[k + 1];
#pragma unroll
        for (int off = 16; off > 0; off >>= 1) {
#pragma unroll
            for (int k = 0; k < KK; k++)
                a[k] += __shfl_down_sync(0xffffffffu, a[k], off);
        }
        if (lane == 0) {
#pragma unroll
            for (int k = 0; k < KK; k++) red[w][k] = a[k];
        }
    }
    __syncthreads();
    if (t < KK * DD) {
        const int k = t >> 3, d = t & 7;        // g_sums layout [k][d]
        atomicAdd(&g_sums[b][k][d], red[d][k]);
    }

    // counts from warp 0 only (each label count <= 32 fits a byte)
    if (w == 0) {
#pragma unroll
        for (int k = 1; k <= KK; k++) {
            unsigned c = (unsigned)((cnt64 >> (8 * k)) & 0xffull);
            c = __reduce_add_sync(0xffffffffu, c);
            if (lane == 0) atomicAdd(&g_cnt[b][k], (int)c);
        }
    }
}

// ---------------------------------------------------------------------------
// Pass 2: per-pixel hinge-variance term (proven shape: smem per-thread slots
// for the 6 label accumulators), centers computed inline in the prologue.
#define T2 256
#define VSLOT 9
#define GX2 128

__device__ __forceinline__ float fsqrt_approx(float x) {
    float r;
    asm("sqrt.approx.f32 %0, %1;" : "=f"(r) : "f"(x));
    return r;
}

__global__ void __launch_bounds__(T2) pass2_kernel(const float* __restrict__ emb,
                                                   const int* __restrict__ mask) {
    __shared__ float4 cs4[(KK + 1) * 2];   // centers table, float4-aligned
    __shared__ float vacc[T2 * VSLOT];
    const int t = threadIdx.x;
    const int b = blockIdx.y;

    if (t < (KK + 1) * DD) {
        const int slot = t / DD, d = t % DD;
        float v = 0.f;
        if (slot >= 1)
            v = g_sums[b][slot - 1][d] / fmaxf((float)g_cnt[b][slot], 1.f);
        reinterpret_cast<float*>(cs4)[t] = v;
    }
#pragma unroll
    for (int j = 0; j < VSLOT; j++) vacc[t * VSLOT + j] = 0.f;
    __syncthreads();

    const float* eb = emb + (size_t)b * DD * PP;
    const int*   mb = mask + (size_t)b * PP;
    const int stride = GX2 * T2 * 4;

    for (int p0 = (blockIdx.x * T2 + t) * 4; p0 < PP; p0 += stride) {
        const int4 lab4 = *reinterpret_cast<const int4*>(mb + p0);
        float ev[4][DD];
#pragma unroll
        for (int d = 0; d < DD; d++) {
            float4 v = *reinterpret_cast<const float4*>(eb + (size_t)d * PP + p0);
            ev[0][d] = v.x; ev[1][d] = v.y; ev[2][d] = v.z; ev[3][d] = v.w;
        }
        int labs[4] = {lab4.x, lab4.y, lab4.z, lab4.w};
#pragma unroll
        for (int i = 0; i < 4; i++) {
            const int lab = labs[i];
            const float4 clo = cs4[lab * 2];
            const float4 chi = cs4[lab * 2 + 1];
            float d0 = ev[i][0] - clo.x;
            float s  = d0 * d0;
            float d1 = ev[i][1] - clo.y; s = fmaf(d1, d1, s);
            float d2 = ev[i][2] - clo.z; s = fmaf(d2, d2, s);
            float d3 = ev[i][3] - clo.w; s = fmaf(d3, d3, s);
            float d4 = ev[i][4] - chi.x; s = fmaf(d4, d4, s);
            float d5 = ev[i][5] - chi.y; s = fmaf(d5, d5, s);
            float d6 = ev[i][6] - chi.z; s = fmaf(d6, d6, s);
            float d7 = ev[i][7] - chi.w; s = fmaf(d7, d7, s);
            // max(sqrt(s)-0.5,0)^2 == s - sqrt(s) + 0.25 when s > 0.25 else 0
            float val = (s - fsqrt_approx(s)) + 0.25f;
            val = (s > 0.25f) ? val : 0.f;
            vacc[t * VSLOT + lab] += val;
        }
    }

    __syncthreads();
    for (int off = T2 / 2; off > 0; off >>= 1) {
        if (t < off) {
            float* a = vacc + t * VSLOT;
            float* c = vacc + (t + off) * VSLOT;
#pragma unroll
            for (int j = 0; j < 6; j++) a[j] += c[j];
        }
        __syncthreads();
    }
    if (t >= 1 && t <= KK) atomicAdd(&g_var[b][t], vacc[t]);
}

// ---------------------------------------------------------------------------
// Finalize: cooperative smem preload of all scratch, per-b epilogue, output
// write, and scratch reset for the next graph replay.
#define TF 320

__global__ void __launch_bounds__(TF) finalize_kernel(float* __restrict__ out) {
    __shared__ float sh_sums[BB][KK][DD];
    __shared__ float sh_cnt[BB][KK + 1];
    __shared__ float sh_varr[BB][KK + 1];
    __shared__ float s_var[BB], s_dist[BB], s_reg[BB], s_has[BB];
    const int t = threadIdx.x;

    if (t < BB * KK * DD) (&sh_sums[0][0][0])[t] = (&g_sums[0][0][0])[t];
    if (t < BB * (KK + 1)) {
        (&sh_cnt[0][0])[t]  = (float)(&g_cnt[0][0])[t];
        (&sh_varr[0][0])[t] = (&g_var[0][0])[t];
    }
    __syncthreads();

    if (t < BB) {
        const int b = t;
        float cnt[KK], present[KK], N = 0.f;
        float ctr[KK][DD];
#pragma unroll
        for (int k = 0; k < KK; k++) {
            cnt[k] = sh_cnt[b][k + 1];
            present[k] = cnt[k] > 0.f ? 1.f : 0.f;
            N += present[k];
            const float inv = 1.f / fmaxf(cnt[k], 1.f);
#pragma unroll
            for (int d = 0; d < DD; d++) ctr[k][d] = sh_sums[b][k][d] * inv;
        }
        float lv = 0.f;
#pragma unroll
        for (int k = 0; k < KK; k++)
            lv += present[k] * (sh_varr[b][k + 1] / fmaxf(cnt[k], 1.f));
        lv /= fmaxf(N, 1.f);

        float ld = 0.f;
        for (int i = 0; i < KK; i++) {
            for (int j = i + 1; j < KK; j++) {
                if (present[i] > 0.f && present[j] > 0.f) {
                    float dsq = 0.f;
#pragma unroll
                    for (int d = 0; d < DD; d++) {
                        float df = ctr[i][d] - ctr[j][d];
                        dsq = fmaf(df, df, dsq);
                    }
                    float dist = sqrtf(dsq);
                    float term = fmaxf(6.0f - dist, 0.f);  // 2*DELTA_D = 6
                    ld += term * term;
                }
            }
        }
        float npairs = N * (N - 1.f) * 0.5f;
        ld /= (N > 1.f) ? npairs : 1.f;

        float lr = 0.f;
#pragma unroll
        for (int k = 0; k < KK; k++) {
            if (present[k] > 0.f) {
                float nsq = 0.f;
#pragma unroll
                for (int d = 0; d < DD; d++) {
                    float c = ctr[k][d];
                    nsq = fmaf(c, c, nsq);
                }
                lr += sqrtf(nsq);
            }
        }
        lr /= fmaxf(N, 1.f);
        s_var[b] = lv; s_dist[b] = ld; s_reg[b] = lr;
        s_has[b] = (N > 0.f) ? 1.f : 0.f;
    }
    __syncthreads();
    if (t == 0) {
        float hv = 0.f, hd = 0.f, hr = 0.f, hh = 0.f;
#pragma unroll
        for (int b = 0; b < BB; b++) {
            hh += s_has[b];
            hv += s_var[b] * s_has[b];
            hd += s_dist[b] * s_has[b];
            hr += s_reg[b] * s_has[b];
        }
        const float den = fmaxf(hh, 1.f);
        const float var = hv / den, dist = hd / den, reg = hr / den;
        out[0] = var + dist + 0.001f * reg;  // ALPHA=BETA=1, GAMMA=0.001
        out[1] = var;
        out[2] = dist;
        out[3] = reg;
    }

    // reset scratch for the next graph replay
    if (t < BB * KK * DD) (&g_sums[0][0][0])[t] = 0.f;
    if (t < BB * (KK + 1)) {
        (&g_cnt[0][0])[t] = 0;
        (&g_var[0][0])[t] = 0.f;
    }
}

// ---------------------------------------------------------------------------
extern "C" void kernel_launch(void* const* d_in, const int* in_sizes, int n_in,
                              void* d_out, int out_size) {
    const float* emb  = (const float*)d_in[0];
    const int*   mask = (const int*)d_in[1];
    float*       out  = (float*)d_out;

    dim3 g1(GX1, BB);
    pass1_kernel<<<g1, T1>>>(emb, mask);
    dim3 g2(GX2, BB);
    pass2_kernel<<<g2, T2>>>(emb, mask);
    finalize_kernel<<<1, TF>>>(out);
}

// round 8
// speedup vs baseline: 1.1395x; 1.1395x over previous
#include <cuda_runtime.h>
#include <cstdint>

#define BB 8
#define DD 8
#define KK 5
#define PP (512*1024)

// ---- scratch (device globals; zero-initialized at module load; finalize
// resets them at the end of every run so graph replays start clean) ----
__device__ float g_sums[BB][KK][DD];   // per-batch per-instance channel sums
__device__ int   g_cnt[BB][KK + 1];    // per-batch per-slot pixel counts
__device__ float g_var[BB][KK + 1];    // per-batch per-slot variance sums

// ---------------------------------------------------------------------------
// Pass 1: channel-split with REGISTER accumulators. Warp w of each block owns
// channel plane w; all 8 warps sweep the same pixel window (mask int4 loads
// dedupe in L1). Each thread keeps only acc[5] registers; per pixel it does 5
// predicated adds. No per-pixel shared-memory traffic at all.
#define T1 256
#define GX1 512
#define ITER1 8
// coverage: GX1 * 32 lanes * 4 px * ITER1 = 524288 = PP exactly

__global__ void __launch_bounds__(T1) pass1_kernel(const float* __restrict__ emb,
                                                   const int* __restrict__ mask) {
    __shared__ float red[DD][KK];
    const int t = threadIdx.x;
    const int b = blockIdx.y;
    const int w = t >> 5, lane = t & 31;   // w = channel index

    float acc[KK];
#pragma unroll
    for (int k = 0; k < KK; k++) acc[k] = 0.f;

    unsigned long long cnt64 = 0ull;
    const float* ep = emb + (size_t)b * DD * PP + (size_t)w * PP;
    const int*   mb = mask + (size_t)b * PP;
    int p = (blockIdx.x * 32 + lane) * 4;
    const int stride = GX1 * 32 * 4;

#pragma unroll
    for (int it = 0; it < ITER1; it++, p += stride) {
        const int4 lab4 = *reinterpret_cast<const int4*>(mb + p);
        const float4 v  = *reinterpret_cast<const float4*>(ep + p);
        const int labs[4] = {lab4.x, lab4.y, lab4.z, lab4.w};
        const float es[4] = {v.x, v.y, v.z, v.w};
#pragma unroll
        for (int i = 0; i < 4; i++) {
            const int lab = labs[i];
            if (w == 0) cnt64 += 1ull << (lab * 8);
#pragma unroll
            for (int k = 0; k < KK; k++)
                acc[k] += (lab == k + 1) ? es[i] : 0.f;
        }
    }

    // per-warp reduction: 5 instance sums for channel w
#pragma unroll
    for (int off = 16; off > 0; off >>= 1) {
#pragma unroll
        for (int k = 0; k < KK; k++)
            acc[k] += __shfl_down_sync(0xffffffffu, acc[k], off);
    }
    if (lane == 0) {
#pragma unroll
        for (int k = 0; k < KK; k++) red[w][k] = acc[k];
    }
    __syncthreads();
    if (t < KK * DD) {
        const int k = t >> 3, d = t & 7;        // g_sums layout [k][d]
        atomicAdd(&g_sums[b][k][d], red[d][k]);
    }

    // counts from warp 0 only (each label count <= 32 fits a byte)
    if (w == 0) {
#pragma unroll
        for (int k = 1; k <= KK; k++) {
            unsigned c = (unsigned)((cnt64 >> (8 * k)) & 0xffull);
            c = __reduce_add_sync(0xffffffffu, c);
            if (lane == 0) atomicAdd(&g_cnt[b][k], (int)c);
        }
    }
}

// ---------------------------------------------------------------------------
// Pass 2: per-pixel hinge-variance term (proven shape: smem per-thread slots
// for the 6 label accumulators), centers computed inline in the prologue.
#define T2 256
#define VSLOT 9
#define GX2 128

__device__ __forceinline__ float fsqrt_approx(float x) {
    float r;
    asm("sqrt.approx.f32 %0, %1;" : "=f"(r) : "f"(x));
    return r;
}

__global__ void __launch_bounds__(T2) pass2_kernel(const float* __restrict__ emb,
                                                   const int* __restrict__ mask) {
    __shared__ float4 cs4[(KK + 1) * 2];   // centers table, float4-aligned
    __shared__ float vacc[T2 * VSLOT];
    const int t = threadIdx.x;
    const int b = blockIdx.y;

    if (t < (KK + 1) * DD) {
        const int slot = t / DD, d = t % DD;
        float v = 0.f;
        if (slot >= 1)
            v = g_sums[b][slot - 1][d] / fmaxf((float)g_cnt[b][slot], 1.f);
        reinterpret_cast<float*>(cs4)[t] = v;
    }
#pragma unroll
    for (int j = 0; j < VSLOT; j++) vacc[t * VSLOT + j] = 0.f;
    __syncthreads();

    const float* eb = emb + (size_t)b * DD * PP;
    const int*   mb = mask + (size_t)b * PP;
    const int stride = GX2 * T2 * 4;

    for (int p0 = (blockIdx.x * T2 + t) * 4; p0 < PP; p0 += stride) {
        const int4 lab4 = *reinterpret_cast<const int4*>(mb + p0);
        float ev[4][DD];
#pragma unroll
        for (int d = 0; d < DD; d++) {
            float4 v = *reinterpret_cast<const float4*>(eb + (size_t)d * PP + p0);
            ev[0][d] = v.x; ev[1][d] = v.y; ev[2][d] = v.z; ev[3][d] = v.w;
        }
        int labs[4] = {lab4.x, lab4.y, lab4.z, lab4.w};
#pragma unroll
        for (int i = 0; i < 4; i++) {
            const int lab = labs[i];
            const float4 clo = cs4[lab * 2];
            const float4 chi = cs4[lab * 2 + 1];
            float d0 = ev[i][0] - clo.x;
            float s  = d0 * d0;
            float d1 = ev[i][1] - clo.y; s = fmaf(d1, d1, s);
            float d2 = ev[i][2] - clo.z; s = fmaf(d2, d2, s);
            float d3 = ev[i][3] - clo.w; s = fmaf(d3, d3, s);
            float d4 = ev[i][4] - chi.x; s = fmaf(d4, d4, s);
            float d5 = ev[i][5] - chi.y; s = fmaf(d5, d5, s);
            float d6 = ev[i][6] - chi.z; s = fmaf(d6, d6, s);
            float d7 = ev[i][7] - chi.w; s = fmaf(d7, d7, s);
            // max(sqrt(s)-0.5,0)^2 == s - sqrt(s) + 0.25 when s > 0.25 else 0
            float val = (s - fsqrt_approx(s)) + 0.25f;
            val = (s > 0.25f) ? val : 0.f;
            vacc[t * VSLOT + lab] += val;
        }
    }

    __syncthreads();
    for (int off = T2 / 2; off > 0; off >>= 1) {
        if (t < off) {
            float* a = vacc + t * VSLOT;
            float* c = vacc + (t + off) * VSLOT;
#pragma unroll
            for (int j = 0; j < 6; j++) a[j] += c[j];
        }
        __syncthreads();
    }
    if (t >= 1 && t <= KK) atomicAdd(&g_var[b][t], vacc[t]);
}

// ---------------------------------------------------------------------------
// Finalize: cooperative smem preload of all scratch, per-b epilogue, output
// write, and scratch reset for the next graph replay.
#define TF 320

__global__ void __launch_bounds__(TF) finalize_kernel(float* __restrict__ out) {
    __shared__ float sh_sums[BB][KK][DD];
    __shared__ float sh_cnt[BB][KK + 1];
    __shared__ float sh_varr[BB][KK + 1];
    __shared__ float s_var[BB], s_dist[BB], s_reg[BB], s_has[BB];
    const int t = threadIdx.x;

    if (t < BB * KK * DD) (&sh_sums[0][0][0])[t] = (&g_sums[0][0][0])[t];
    if (t < BB * (KK + 1)) {
        (&sh_cnt[0][0])[t]  = (float)(&g_cnt[0][0])[t];
        (&sh_varr[0][0])[t] = (&g_var[0][0])[t];
    }
    __syncthreads();

    if (t < BB) {
        const int b = t;
        float cnt[KK], present[KK], N = 0.f;
        float ctr[KK][DD];
#pragma unroll
        for (int k = 0; k < KK; k++) {
            cnt[k] = sh_cnt[b][k + 1];
            present[k] = cnt[k] > 0.f ? 1.f : 0.f;
            N += present[k];
            const float inv = 1.f / fmaxf(cnt[k], 1.f);
#pragma unroll
            for (int d = 0; d < DD; d++) ctr[k][d] = sh_sums[b][k][d] * inv;
        }
        float lv = 0.f;
#pragma unroll
        for (int k = 0; k < KK; k++)
            lv += present[k] * (sh_varr[b][k + 1] / fmaxf(cnt[k], 1.f));
        lv /= fmaxf(N, 1.f);

        float ld = 0.f;
        for (int i = 0; i < KK; i++) {
            for (int j = i + 1; j < KK; j++) {
                if (present[i] > 0.f && present[j] > 0.f) {
                    float dsq = 0.f;
#pragma unroll
                    for (int d = 0; d < DD; d++) {
                        float df = ctr[i][d] - ctr[j][d];
                        dsq = fmaf(df, df, dsq);
                    }
                    float dist = sqrtf(dsq);
                    float term = fmaxf(6.0f - dist, 0.f);  // 2*DELTA_D = 6
                    ld += term * term;
                }
            }
        }
        float npairs = N * (N - 1.f) * 0.5f;
        ld /= (N > 1.f) ? npairs : 1.f;

        float lr = 0.f;
#pragma unroll
        for (int k = 0; k < KK; k++) {
            if (present[k] > 0.f) {
                float nsq = 0.f;
#pragma unroll
                for (int d = 0; d < DD; d++) {
                    float c = ctr[k][d];
                    nsq = fmaf(c, c, nsq);
                }
                lr += sqrtf(nsq);
            }
        }
        lr /= fmaxf(N, 1.f);
        s_var[b] = lv; s_dist[b] = ld; s_reg[b] = lr;
        s_has[b] = (N > 0.f) ? 1.f : 0.f;
    }
    __syncthreads();
    if (t == 0) {
        float hv = 0.f, hd = 0.f, hr = 0.f, hh = 0.f;
#pragma unroll
        for (int b = 0; b < BB; b++) {
            hh += s_has[b];
            hv += s_var[b] * s_has[b];
            hd += s_dist[b] * s_has[b];
            hr += s_reg[b] * s_has[b];
        }
        const float den = fmaxf(hh, 1.f);
        const float var = hv / den, dist = hd / den, reg = hr / den;
        out[0] = var + dist + 0.001f * reg;  // ALPHA=BETA=1, GAMMA=0.001
        out[1] = var;
        out[2] = dist;
        out[3] = reg;
    }

    // reset scratch for the next graph replay
    if (t < BB * KK * DD) (&g_sums[0][0][0])[t] = 0.f;
    if (t < BB * (KK + 1)) {
        (&g_cnt[0][0])[t] = 0;
        (&g_var[0][0])[t] = 0.f;
    }
}

// ---------------------------------------------------------------------------
extern "C" void kernel_launch(void* const* d_in, const int* in_sizes, int n_in,
                              void* d_out, int out_size) {
    const float* emb  = (const float*)d_in[0];
    const int*   mask = (const int*)d_in[1];
    float*       out  = (float*)d_out;

    dim3 g1(GX1, BB);
    pass1_kernel<<<g1, T1>>>(emb, mask);
    dim3 g2(GX2, BB);
    pass2_kernel<<<g2, T2>>>(emb, mask);
    finalize_kernel<<<1, TF>>>(out);
}